// round 16
// baseline (speedup 1.0000x reference)
#include <cuda_runtime.h>
#include <cstdint>

#define NODES 336
#define NPC   8192
#define NUMCASE 2048
#define MIU_F 1.9e-05f
#define ALPHA_F 0.10471975511965977f   // 6*pi/180
#define QCOEF_F 73830.75f              // 0.5*1.225*ACOUSTIC^2
#define FULL 0xffffffffu
#define DSG_BYTES (NODES * 5 * 4)      // 6720, 16B multiple; src 16B-aligned

__device__ __forceinline__ uint32_t smem_u32(const void* p) {
    return (uint32_t)__cvta_generic_to_shared(p);
}

// One barrier for the stencil, one MUFU per node (tau = MIU*(f.T)*rsqrt(|T|^2|d|^2)),
// index-shift friction identity (no tau smem round-trip), and the design slab
// fetched by ONE cp.async.bulk overlapped with everything else.
__global__ __launch_bounds__(128, 12) void dyn_kernel(
    const float* __restrict__ coords,
    const float* __restrict__ fields,
    const float* __restrict__ design,
    float2* __restrict__ out)
{
    const int c = blockIdx.x;
    const int base = c * NPC;
    const int t = threadIdx.x;

    __shared__ alignas(16) float s_dsg[NODES * 5];
    __shared__ float2 s_n0[NODES];
    __shared__ float  s_red[4][4];
    __shared__ alignas(8) uint64_t mbar;

    // ---- t0: init mbar + launch bulk copy of the design slab ----
    if (t == 0) {
        uint32_t mb = smem_u32(&mbar);
        asm volatile("mbarrier.init.shared.b64 [%0], 1;" :: "r"(mb) : "memory");
        asm volatile("fence.proxy.async.shared::cta;" ::: "memory");
        asm volatile("mbarrier.arrive.expect_tx.shared.b64 _, [%0], %1;" ::
                     "r"(mb), "r"((uint32_t)DSG_BYTES) : "memory");
        asm volatile("cp.async.bulk.shared::cta.global.mbarrier::complete_tx::bytes [%0], [%1], %2, [%3];"
                     :: "r"(smem_u32(s_dsg)),
                        "l"((const char*)(design + (size_t)base * 5)),
                        "r"((uint32_t)DSG_BYTES), "r"(mb) : "memory");
    }

    // ---- front-batched LDGs: coords + f1zw + pt only (12/thread) ----
    float2 n0[3], n1[3];
    float f1u[3], f1v[3], pt[3];
    const float2* cf2 = (const float2*)coords;
    #pragma unroll
    for (int k = 0; k < 3; k++) {
        int j = t + k * 128;
        bool valid = (k < 2) || (t < NODES - 256);
        if (valid) {
            n0[k] = cf2[base + j];
            n1[k] = cf2[base + NODES + j];
            float2 f1zw = *(const float2*)(fields + 4 * (base + NODES + j) + 2);
            f1u[k] = f1zw.x;
            f1v[k] = f1zw.y;
            pt[k]  = fields[4 * (base + j)];          // f0[:, :, 0]
            s_n0[j] = n0[k];
        }
    }
    __syncthreads();   // s_n0 ready (also orders mbar.init before any wait)

    // ---- forces: tau once per node, friction uses (T[j]+T[j-1])/2 ----
    float Fx = 0.f, Fy = 0.f;
    #pragma unroll
    for (int k = 0; k < 3; k++) {
        int j = t + k * 128;
        bool valid = (k < 2) || (t < NODES - 256);
        if (valid) {
            int jp = (j + 1 == NODES) ? 0 : j + 1;
            int jm = (j == 0) ? NODES - 1 : j - 1;
            float2 np = s_n0[jp];
            float2 nm = s_n0[jm];
            float tx  = np.x - n0[k].x, ty  = np.y - n0[k].y;   // T[j]
            float txm = n0[k].x - nm.x, tym = n0[k].y - nm.y;   // T[j-1]
            float tn2 = tx * tx + ty * ty;
            float dx = n1[k].x - n0[k].x, dy = n1[k].y - n0[k].y;
            float dl2 = dx * dx + dy * dy;
            float tau = MIU_F * (f1u[k] * tx + f1v[k] * ty) * rsqrtf(tn2 * dl2);
            float t50 = 50.f * tau;
            Fx += -pt[k] * ty + t50 * (0.5f * (tx + txm));
            Fy +=  pt[k] * tx + t50 * (0.5f * (ty + tym));
        }
    }

    // ---- wait for the design slab (long since landed), sum cols 3,4 ----
    {
        uint32_t mb = smem_u32(&mbar);
        uint32_t done;
        asm volatile(
            "{\n\t.reg .pred p;\n\t"
            "mbarrier.try_wait.parity.acquire.cta.shared::cta.b64 p, [%1], 0;\n\t"
            "selp.b32 %0, 1, 0, p;\n\t}"
            : "=r"(done) : "r"(mb) : "memory");
        while (!done) {
            asm volatile(
                "{\n\t.reg .pred p;\n\t"
                "mbarrier.try_wait.parity.acquire.cta.shared::cta.b64 p, [%1], 0, 0x989680;\n\t"
                "selp.b32 %0, 1, 0, p;\n\t}"
                : "=r"(done) : "r"(mb) : "memory");
        }
    }
    float d3 = 0.f, d4 = 0.f;
    #pragma unroll
    for (int k = 0; k < 3; k++) {
        int j = t + k * 128;
        bool valid = (k < 2) || (t < NODES - 256);
        if (valid) {
            d3 += s_dsg[5 * j + 3];   // stride-5 floats: conflict-free (gcd(5,32)=1)
            d4 += s_dsg[5 * j + 4];
        }
    }

    // ---- block reduction over 4 warps ----
    #pragma unroll
    for (int off = 16; off; off >>= 1) {
        Fx += __shfl_down_sync(FULL, Fx, off);
        Fy += __shfl_down_sync(FULL, Fy, off);
        d3 += __shfl_down_sync(FULL, d3, off);
        d4 += __shfl_down_sync(FULL, d4, off);
    }
    int warp = t >> 5, lane = t & 31;
    if (lane == 0) {
        s_red[warp][0] = Fx;
        s_red[warp][1] = Fy;
        s_red[warp][2] = d3;
        s_red[warp][3] = d4;
    }
    __syncthreads();

    if (t == 0) {
        float fx = 0.f, fy = 0.f, s3 = 0.f, s4 = 0.f;
        #pragma unroll
        for (int w = 0; w < 4; w++) {
            fx += s_red[w][0];
            fy += s_red[w][1];
            s3 += s_red[w][2];
            s4 += s_red[w][3];
        }
        float Ma = s3 * (0.3f / (float)NODES) + 0.3f;
        float af = s4 * (ALPHA_F / (float)NODES);
        float ca = cosf(af), sa = sinf(af);
        float Fxn = fx * ca + fy * sa;
        float Fyn = fy * ca - Fxn * sa;   // reference uses Fx_new here (literal)
        float q = QCOEF_F * Ma * Ma;
        out[c] = make_float2(Fxn / q, Fyn / q);
    }
}

extern "C" void kernel_launch(void* const* d_in, const int* in_sizes, int n_in,
                              void* d_out, int out_size) {
    // metadata order: batch(int32), coords(f32), fields(f32), design(f32), num_case, nodes_num
    const float* coords = (const float*)d_in[1];
    const float* fields = (const float*)d_in[2];
    const float* design = (const float*)d_in[3];
    float2* out = (float2*)d_out;
    dyn_kernel<<<NUMCASE, 128>>>(coords, fields, design, out);
}

// round 17
// speedup vs baseline: 1.2610x; 1.2610x over previous
#include <cuda_runtime.h>

#define NODES 336
#define NPC   8192
#define NUMCASE 2048
#define MIU_F 1.9e-05f
#define ALPHA_F 0.10471975511965977f   // 6*pi/180
#define QCOEF_F 73830.75f              // 0.5*1.225*ACOUSTIC^2
#define FULL 0xffffffffu
#define DSG_F4 420                     // 336*5/4 float4s per case

// R14 base (one barrier, one MUFU/node, index-shift friction identity)
// + dense float4 sweep of the design slab (alignment-safe, half the wavefronts).
__global__ __launch_bounds__(96, 14) void dyn_kernel(
    const float* __restrict__ coords,
    const float* __restrict__ fields,
    const float* __restrict__ design,
    float2* __restrict__ out)
{
    const int c = blockIdx.x;
    const int base = c * NPC;
    const int t = threadIdx.x;

    __shared__ float2 s_n0[NODES];
    __shared__ float  s_red[3][4];

    float2 n0[4], n1[4];
    float f1u[4], f1v[4], pt[4];
    float d3 = 0.f, d4 = 0.f;

    const float2* cf2 = (const float2*)coords;

    // ---- dense design slab: 420 float4, mod-5 component select ----
    {
        const float4* dsg4 = (const float4*)(design + (size_t)base * 5);
        #pragma unroll
        for (int k = 0; k < 5; k++) {
            int idx = t + k * 96;
            if (idx < DSG_F4) {
                float4 v = __ldg(&dsg4[idx]);
                int r = (4 * idx) % 5;      // component of v.x
                switch (r) {
                    case 0: d3 += v.w; break;
                    case 1: d3 += v.z; d4 += v.w; break;
                    case 2: d3 += v.y; d4 += v.z; break;
                    case 3: d3 += v.x; d4 += v.y; break;
                    default: d4 += v.x; break;   // r == 4
                }
            }
        }
    }

    // ---- front-batched stencil loads ----
    #pragma unroll
    for (int k = 0; k < 4; k++) {
        int j = t + k * 96;
        bool valid = (k < 3) || (t < NODES - 288);
        if (valid) {
            n0[k] = cf2[base + j];
            n1[k] = cf2[base + NODES + j];
            float2 f1zw = *(const float2*)(fields + 4 * (base + NODES + j) + 2);
            f1u[k] = f1zw.x;
            f1v[k] = f1zw.y;
            pt[k]  = fields[4 * (base + j)];          // f0[:, :, 0]
            s_n0[j] = n0[k];
        }
    }
    __syncthreads();

    // ---- forces: tau once per node, friction uses (T[j]+T[j-1])/2 ----
    float Fx = 0.f, Fy = 0.f;
    #pragma unroll
    for (int k = 0; k < 4; k++) {
        int j = t + k * 96;
        bool valid = (k < 3) || (t < NODES - 288);
        if (valid) {
            int jp = (j + 1 == NODES) ? 0 : j + 1;
            int jm = (j == 0) ? NODES - 1 : j - 1;
            float2 np = s_n0[jp];
            float2 nm = s_n0[jm];
            float tx  = np.x - n0[k].x, ty  = np.y - n0[k].y;   // T[j]
            float txm = n0[k].x - nm.x, tym = n0[k].y - nm.y;   // T[j-1]
            float tn2 = tx * tx + ty * ty;
            float dx = n1[k].x - n0[k].x, dy = n1[k].y - n0[k].y;
            float dl2 = dx * dx + dy * dy;
            float tau = MIU_F * (f1u[k] * tx + f1v[k] * ty) * rsqrtf(tn2 * dl2);
            float t50 = 50.f * tau;
            Fx += -pt[k] * ty + t50 * (0.5f * (tx + txm));
            Fy +=  pt[k] * tx + t50 * (0.5f * (ty + tym));
        }
    }

    // ---- block reduction over 3 warps ----
    #pragma unroll
    for (int off = 16; off; off >>= 1) {
        Fx += __shfl_down_sync(FULL, Fx, off);
        Fy += __shfl_down_sync(FULL, Fy, off);
        d3 += __shfl_down_sync(FULL, d3, off);
        d4 += __shfl_down_sync(FULL, d4, off);
    }
    int warp = t >> 5, lane = t & 31;
    if (lane == 0) {
        s_red[warp][0] = Fx;
        s_red[warp][1] = Fy;
        s_red[warp][2] = d3;
        s_red[warp][3] = d4;
    }
    __syncthreads();

    if (t == 0) {
        float fx = s_red[0][0] + s_red[1][0] + s_red[2][0];
        float fy = s_red[0][1] + s_red[1][1] + s_red[2][1];
        float s3 = s_red[0][2] + s_red[1][2] + s_red[2][2];
        float s4 = s_red[0][3] + s_red[1][3] + s_red[2][3];
        float Ma = s3 * (0.3f / (float)NODES) + 0.3f;
        float af = s4 * (ALPHA_F / (float)NODES);
        float ca = cosf(af), sa = sinf(af);
        float Fxn = fx * ca + fy * sa;
        float Fyn = fy * ca - Fxn * sa;   // reference uses Fx_new here (literal)
        float q = QCOEF_F * Ma * Ma;
        out[c] = make_float2(Fxn / q, Fyn / q);
    }
}

extern "C" void kernel_launch(void* const* d_in, const int* in_sizes, int n_in,
                              void* d_out, int out_size) {
    // metadata order: batch(int32), coords(f32), fields(f32), design(f32), num_case, nodes_num
    const float* coords = (const float*)d_in[1];
    const float* fields = (const float*)d_in[2];
    const float* design = (const float*)d_in[3];
    float2* out = (float2*)d_out;
    dyn_kernel<<<NUMCASE, 96>>>(coords, fields, design, out);
}